// round 14
// baseline (speedup 1.0000x reference)
#include <cuda_runtime.h>
#include <cuda_bf16.h>
#include <cstddef>

// WeaveLayer: pure permutation
//   out[b, yb*8 + hi*4 + px, xb*8 + wi*4 + py] = in[b, yb*4+py, xb*4+px, hi*2+wi]
// Shapes: in (B, 768, 768, 4) f32, out (B, 1536, 1536, 1) f32, n=4 fixed.
//
// R12/R13: 90.2us, DRAM ~79.7% active (idle 20%), HBM 6.3 TB/s.
// R14 change: 8x larger CTA tile — one CTA handles a full yb stripe
// (4 input rows x 768 px  ->  8 complete 6KB-contiguous output rows).
// Tests whether DRAM idle cycles come from fine-grained burst fragmentation
// (36864 small tiles) vs an inherent rd/wr turnaround ceiling.
//
// 512 threads, 48KB static smem (8 x 1536 floats), 4 CTAs/SM.

#define IN_W   768
#define OUT_W  1536
#define SROW   1536   // floats per smem row (exactly 48KB total, float4-aligned)

__global__ __launch_bounds__(512, 4)
void weave_kernel(const float4* __restrict__ in, float* __restrict__ out)
{
    __shared__ float sm[8 * SROW];   // 49152 B

    const int tid = threadIdx.x;
    const int yb  = blockIdx.x;      // 0..191
    const int b   = blockIdx.y;      // 0..B-1

    // ---- Load + scatter: 4 input rows x 768 pixels (float4 each) ----
    const float4* inb = in + ((size_t)b * IN_W + (size_t)yb * 4) * IN_W;

#pragma unroll
    for (int it = 0; it < 6; it++) {
        int i  = tid + it * 512;     // 0..3071
        int py = i / IN_W;           // 0..3
        int lx = i - py * IN_W;      // 0..767
        float4 v = __ldcs(&inb[py * IN_W + lx]);

        int px = lx & 3;             // pixel-in-patch (x)
        int c0 = (lx >> 2) * 8 + py; // xb*8 + py  (wi=0 column)
        // q = hi*2 + wi ; smem row = hi*4 + px ; col = xb*8 + wi*4 + py
        sm[ px      * SROW + c0    ] = v.x;   // q=0 (hi=0, wi=0)
        sm[ px      * SROW + c0 + 4] = v.y;   // q=1 (hi=0, wi=1)
        sm[(px + 4) * SROW + c0    ] = v.z;   // q=2 (hi=1, wi=0)
        sm[(px + 4) * SROW + c0 + 4] = v.w;   // q=3 (hi=1, wi=1)
    }

    __syncthreads();

    // ---- Store: 8 full output rows x 1536 cols, coalesced float4 ----
    const float4* sm4 = reinterpret_cast<const float4*>(sm);
    float4* outb = reinterpret_cast<float4*>(
        out + ((size_t)b * OUT_W + (size_t)yb * 8) * OUT_W);

#pragma unroll
    for (int it = 0; it < 6; it++) {
        int i = tid + it * 512;      // 0..3071 == orow*384 + c4
        __stcs(&outb[i], sm4[i]);
    }
}

extern "C" void kernel_launch(void* const* d_in, const int* in_sizes, int n_in,
                              void* d_out, int out_size)
{
    const float4* in  = reinterpret_cast<const float4*>(d_in[0]);
    float*        out = reinterpret_cast<float*>(d_out);

    int B = in_sizes[0] / (IN_W * IN_W * 4);

    dim3 grid(IN_W / 4,   // 192 yb stripes
              B);         // 32
    weave_kernel<<<grid, 512>>>(in, out);
}

// round 15
// speedup vs baseline: 1.0082x; 1.0082x over previous
#include <cuda_runtime.h>
#include <cuda_bf16.h>
#include <cstddef>

// WeaveLayer: pure permutation
//   out[b, yb*8 + hi*4 + px, xb*8 + wi*4 + py] = in[b, yb*4+py, xb*4+px, hi*2+wi]
// Shapes: in (B, 768, 768, 4) f32, out (B, 1536, 1536, 1) f32, n=4 fixed.
//
// R12/R13: 90.2us, DRAM ~79.7% active (idle 20%), HBM 6.3 TB/s.
// R14 change: 8x larger CTA tile — one CTA handles a full yb stripe
// (4 input rows x 768 px  ->  8 complete 6KB-contiguous output rows).
// Tests whether DRAM idle cycles come from fine-grained burst fragmentation
// (36864 small tiles) vs an inherent rd/wr turnaround ceiling.
//
// 512 threads, 48KB static smem (8 x 1536 floats), 4 CTAs/SM.

#define IN_W   768
#define OUT_W  1536
#define SROW   1536   // floats per smem row (exactly 48KB total, float4-aligned)

__global__ __launch_bounds__(512, 4)
void weave_kernel(const float4* __restrict__ in, float* __restrict__ out)
{
    __shared__ float sm[8 * SROW];   // 49152 B

    const int tid = threadIdx.x;
    const int yb  = blockIdx.x;      // 0..191
    const int b   = blockIdx.y;      // 0..B-1

    // ---- Load + scatter: 4 input rows x 768 pixels (float4 each) ----
    const float4* inb = in + ((size_t)b * IN_W + (size_t)yb * 4) * IN_W;

#pragma unroll
    for (int it = 0; it < 6; it++) {
        int i  = tid + it * 512;     // 0..3071
        int py = i / IN_W;           // 0..3
        int lx = i - py * IN_W;      // 0..767
        float4 v = __ldcs(&inb[py * IN_W + lx]);

        int px = lx & 3;             // pixel-in-patch (x)
        int c0 = (lx >> 2) * 8 + py; // xb*8 + py  (wi=0 column)
        // q = hi*2 + wi ; smem row = hi*4 + px ; col = xb*8 + wi*4 + py
        sm[ px      * SROW + c0    ] = v.x;   // q=0 (hi=0, wi=0)
        sm[ px      * SROW + c0 + 4] = v.y;   // q=1 (hi=0, wi=1)
        sm[(px + 4) * SROW + c0    ] = v.z;   // q=2 (hi=1, wi=0)
        sm[(px + 4) * SROW + c0 + 4] = v.w;   // q=3 (hi=1, wi=1)
    }

    __syncthreads();

    // ---- Store: 8 full output rows x 1536 cols, coalesced float4 ----
    const float4* sm4 = reinterpret_cast<const float4*>(sm);
    float4* outb = reinterpret_cast<float4*>(
        out + ((size_t)b * OUT_W + (size_t)yb * 8) * OUT_W);

#pragma unroll
    for (int it = 0; it < 6; it++) {
        int i = tid + it * 512;      // 0..3071 == orow*384 + c4
        __stcs(&outb[i], sm4[i]);
    }
}

extern "C" void kernel_launch(void* const* d_in, const int* in_sizes, int n_in,
                              void* d_out, int out_size)
{
    const float4* in  = reinterpret_cast<const float4*>(d_in[0]);
    float*        out = reinterpret_cast<float*>(d_out);

    int B = in_sizes[0] / (IN_W * IN_W * 4);

    dim3 grid(IN_W / 4,   // 192 yb stripes
              B);         // 32
    weave_kernel<<<grid, 512>>>(in, out);
}

// round 16
// speedup vs baseline: 1.0085x; 1.0003x over previous
#include <cuda_runtime.h>
#include <cuda_bf16.h>
#include <cstddef>

// WeaveLayer: pure permutation
//   out[b, yb*8 + hi*4 + px, xb*8 + wi*4 + py] = in[b, yb*4+py, xb*4+px, hi*2+wi]
// Shapes: in (B, 768, 768, 4) f32, out (B, 1536, 1536, 1) f32, n=4 fixed.
//
// R12/R13: 90.2us, DRAM ~79.7% active (idle 20%), HBM 6.3 TB/s.
// R14 change: 8x larger CTA tile — one CTA handles a full yb stripe
// (4 input rows x 768 px  ->  8 complete 6KB-contiguous output rows).
// Tests whether DRAM idle cycles come from fine-grained burst fragmentation
// (36864 small tiles) vs an inherent rd/wr turnaround ceiling.
//
// 512 threads, 48KB static smem (8 x 1536 floats), 4 CTAs/SM.

#define IN_W   768
#define OUT_W  1536
#define SROW   1536   // floats per smem row (exactly 48KB total, float4-aligned)

__global__ __launch_bounds__(512, 4)
void weave_kernel(const float4* __restrict__ in, float* __restrict__ out)
{
    __shared__ float sm[8 * SROW];   // 49152 B

    const int tid = threadIdx.x;
    const int yb  = blockIdx.x;      // 0..191
    const int b   = blockIdx.y;      // 0..B-1

    // ---- Load + scatter: 4 input rows x 768 pixels (float4 each) ----
    const float4* inb = in + ((size_t)b * IN_W + (size_t)yb * 4) * IN_W;

#pragma unroll
    for (int it = 0; it < 6; it++) {
        int i  = tid + it * 512;     // 0..3071
        int py = i / IN_W;           // 0..3
        int lx = i - py * IN_W;      // 0..767
        float4 v = __ldcs(&inb[py * IN_W + lx]);

        int px = lx & 3;             // pixel-in-patch (x)
        int c0 = (lx >> 2) * 8 + py; // xb*8 + py  (wi=0 column)
        // q = hi*2 + wi ; smem row = hi*4 + px ; col = xb*8 + wi*4 + py
        sm[ px      * SROW + c0    ] = v.x;   // q=0 (hi=0, wi=0)
        sm[ px      * SROW + c0 + 4] = v.y;   // q=1 (hi=0, wi=1)
        sm[(px + 4) * SROW + c0    ] = v.z;   // q=2 (hi=1, wi=0)
        sm[(px + 4) * SROW + c0 + 4] = v.w;   // q=3 (hi=1, wi=1)
    }

    __syncthreads();

    // ---- Store: 8 full output rows x 1536 cols, coalesced float4 ----
    const float4* sm4 = reinterpret_cast<const float4*>(sm);
    float4* outb = reinterpret_cast<float4*>(
        out + ((size_t)b * OUT_W + (size_t)yb * 8) * OUT_W);

#pragma unroll
    for (int it = 0; it < 6; it++) {
        int i = tid + it * 512;      // 0..3071 == orow*384 + c4
        __stcs(&outb[i], sm4[i]);
    }
}

extern "C" void kernel_launch(void* const* d_in, const int* in_sizes, int n_in,
                              void* d_out, int out_size)
{
    const float4* in  = reinterpret_cast<const float4*>(d_in[0]);
    float*        out = reinterpret_cast<float*>(d_out);

    int B = in_sizes[0] / (IN_W * IN_W * 4);

    dim3 grid(IN_W / 4,   // 192 yb stripes
              B);         // 32
    weave_kernel<<<grid, 512>>>(in, out);
}

// round 17
// speedup vs baseline: 1.2048x; 1.1947x over previous
#include <cuda_runtime.h>
#include <cuda_bf16.h>
#include <cstddef>

// WeaveLayer: pure permutation
//   out[b, yb*8 + hi*4 + px, xb*8 + wi*4 + py] = in[b, yb*4+py, xb*4+px, hi*2+wi]
// Shapes: in (B, 768, 768, 4) f32, out (B, 1536, 1536, 1) f32, n=4 fixed.
//
// R12 (best): 90.2us, DRAM 79.9%, L1 65.6% (4-way-conflicted scalar STS).
// R16 (big tile): 109us — SROW%32==0 collapsed STS banks to 8-way; reverted.
//
// R17: register-transpose variant. One thread = one input pixel column:
// loads 4 float4s (py=0..3, same lx), transposes py in registers, writes
// 4x STS.128 (2-way conflicts w/ SROW4=65) instead of 16x STS.32 (4-way).
// Same R12 tile: one yb x 32 xb blocks (128 in-pixels -> 8x256 out).

#define IN_W    768
#define OUT_W   1536
#define SROW4   65    // float4s per smem row (65*16B=1040B: bank-rotating pad)

__global__ __launch_bounds__(128, 12)
void weave_kernel(const float4* __restrict__ in, float* __restrict__ out)
{
    __shared__ float4 sm4[8 * SROW4];   // 8320 B

    const int lx = threadIdx.x;          // pixel column 0..127
    const int b  = blockIdx.z;
    const int yb = blockIdx.y;           // 0..191
    const int x0 = blockIdx.x * 128;     // input pixel base

    // ---- Load: 4 rows, same lx — coalesced, MLP=4 front-batched ----
    const float4* inb = in + ((size_t)b * IN_W + (size_t)yb * 4) * IN_W + x0 + lx;
    float4 v0 = __ldcs(&inb[0 * IN_W]);
    float4 v1 = __ldcs(&inb[1 * IN_W]);
    float4 v2 = __ldcs(&inb[2 * IN_W]);
    float4 v3 = __ldcs(&inb[3 * IN_W]);

    // ---- Register transpose + STS.128 scatter ----
    // q = hi*2+wi ; smem row = hi*4+px ; col4 = xbl*2+wi
    const int px  = lx & 3;
    const int xbl = lx >> 2;             // 0..31
    const int c4  = xbl * 2;

    // q=0 (hi=0, wi=0): out cols xb*8 + 0..3  (py fastest)
    sm4[ px      * SROW4 + c4    ] = make_float4(v0.x, v1.x, v2.x, v3.x);
    // q=1 (hi=0, wi=1): out cols xb*8 + 4..7
    sm4[ px      * SROW4 + c4 + 1] = make_float4(v0.y, v1.y, v2.y, v3.y);
    // q=2 (hi=1, wi=0)
    sm4[(px + 4) * SROW4 + c4    ] = make_float4(v0.z, v1.z, v2.z, v3.z);
    // q=3 (hi=1, wi=1)
    sm4[(px + 4) * SROW4 + c4 + 1] = make_float4(v0.w, v1.w, v2.w, v3.w);

    __syncthreads();

    // ---- Store: 8 output rows x 64 float4 cols, fully coalesced ----
    float4* outb = reinterpret_cast<float4*>(
        out + ((size_t)b * OUT_W + (size_t)yb * 8) * OUT_W + blockIdx.x * 256);

#pragma unroll
    for (int it = 0; it < 4; it++) {
        int i    = lx + it * 128;        // 0..511
        int orow = i >> 6;               // 0..7
        int oc4  = i & 63;               // 0..63
        __stcs(&outb[orow * (OUT_W / 4) + oc4], sm4[orow * SROW4 + oc4]);
    }
}

extern "C" void kernel_launch(void* const* d_in, const int* in_sizes, int n_in,
                              void* d_out, int out_size)
{
    const float4* in  = reinterpret_cast<const float4*>(d_in[0]);
    float*        out = reinterpret_cast<float*>(d_out);

    int B = in_sizes[0] / (IN_W * IN_W * 4);

    dim3 grid(IN_W / 128,   // 6  : x tiles (128 input pixels each)
              IN_W / 4,     // 192: yb stripes
              B);           // 32
    weave_kernel<<<grid, 128>>>(in, out);
}